// round 5
// baseline (speedup 1.0000x reference)
#include <cuda_runtime.h>
#include <math.h>

// Problem constants
#define Bb      2
#define Nn      2048
#define Cc      1024
#define Hh      16
#define Dd      64
#define MROWS   (Bb * Nn)      // 4096
#define THREEC  (3 * Cc)       // 3072
#define LOGMAX  4.6051701859880914f  // ln(100)

// ---------------------------------------------------------------------------
// Scratch (static device globals; no runtime allocation allowed)
// ---------------------------------------------------------------------------
__device__ float g_qkv[(size_t)MROWS * THREEC];          // 50 MB  [4096][3072]
__device__ float g_scores[(size_t)Bb * Hh * Nn * Nn];    // 512 MB [B*H][N][N]
__device__ float g_att[(size_t)MROWS * Cc];              // 16 MB  [4096][1024]

__device__ __forceinline__ float neg_inf() { return __int_as_float(0xff800000); }

// ---------------------------------------------------------------------------
// Generic NT SGEMM: C[M][Ncols] = A[M][K] * W[Ncols][K]^T (+ bias)
// 64x64 tile, BK=16, 256 threads, 4x4 per-thread micro-tile.
// ---------------------------------------------------------------------------
__global__ __launch_bounds__(256) void sgemm_nt(
    const float* __restrict__ A, const float* __restrict__ W,
    const float* __restrict__ bias, float* __restrict__ C,
    int M, int Ncols, int K)
{
    __shared__ __align__(16) float As[16][68];   // [k][m]
    __shared__ __align__(16) float Ws[16][68];   // [k][n]
    const int tid = threadIdx.x;
    const int tx = tid & 15, ty = tid >> 4;
    const int m0 = blockIdx.y * 64, n0 = blockIdx.x * 64;
    const int r = tid >> 2, c4 = tid & 3;

    float acc[4][4] = {};

    for (int kt = 0; kt < K; kt += 16) {
        float4 av = *reinterpret_cast<const float4*>(&A[(size_t)(m0 + r) * K + kt + c4 * 4]);
        float4 wv = *reinterpret_cast<const float4*>(&W[(size_t)(n0 + r) * K + kt + c4 * 4]);
        __syncthreads();
        As[c4 * 4 + 0][r] = av.x; As[c4 * 4 + 1][r] = av.y;
        As[c4 * 4 + 2][r] = av.z; As[c4 * 4 + 3][r] = av.w;
        Ws[c4 * 4 + 0][r] = wv.x; Ws[c4 * 4 + 1][r] = wv.y;
        Ws[c4 * 4 + 2][r] = wv.z; Ws[c4 * 4 + 3][r] = wv.w;
        __syncthreads();
        #pragma unroll
        for (int k = 0; k < 16; ++k) {
            float4 a4 = *reinterpret_cast<const float4*>(&As[k][ty * 4]);
            float4 b4 = *reinterpret_cast<const float4*>(&Ws[k][tx * 4]);
            float a[4] = {a4.x, a4.y, a4.z, a4.w};
            float b[4] = {b4.x, b4.y, b4.z, b4.w};
            #pragma unroll
            for (int i = 0; i < 4; ++i)
                #pragma unroll
                for (int j = 0; j < 4; ++j)
                    acc[i][j] = fmaf(a[i], b[j], acc[i][j]);
        }
    }

    #pragma unroll
    for (int i = 0; i < 4; ++i) {
        int m = m0 + ty * 4 + i;
        #pragma unroll
        for (int j = 0; j < 4; ++j) {
            int n = n0 + tx * 4 + j;
            float v = acc[i][j];
            if (bias) v += bias[n];
            C[(size_t)m * Ncols + n] = v;
        }
    }
}

// ---------------------------------------------------------------------------
// Normalize q and k head-rows (D=64) in place. One warp per (row, s, h).
// ---------------------------------------------------------------------------
__global__ __launch_bounds__(256) void norm_qk(float* __restrict__ qkv)
{
    int warp = (blockIdx.x * blockDim.x + threadIdx.x) >> 5;
    int lane = threadIdx.x & 31;
    int m = warp >> 5;          // row 0..4095
    int rem = warp & 31;
    int s = rem >> 4;           // 0 (q) or 1 (k)
    int h = rem & 15;
    float* row = qkv + (size_t)m * THREEC + s * Cc + h * Dd;
    float v0 = row[lane], v1 = row[lane + 32];
    float ss = v0 * v0 + v1 * v1;
    #pragma unroll
    for (int o = 16; o; o >>= 1) ss += __shfl_xor_sync(0xffffffffu, ss, o);
    float inv = rsqrtf(ss);
    row[lane] = v0 * inv;
    row[lane + 32] = v1 * inv;
}

// ---------------------------------------------------------------------------
// Scores: S[b,h,q,k] = scale_h * dot(qn, kn) + alibi; mask -> -inf
// Per block: 64(q) x 64(k) tile, K-dim = D = 64. 256 threads, 4x4 micro-tile.
// ---------------------------------------------------------------------------
__global__ __launch_bounds__(256) void scores_kernel(
    const float* __restrict__ alibi,
    const int* __restrict__ mask,              // bool materialized as int32
    const float* __restrict__ logit_scale)
{
    __shared__ __align__(16) float Qs[64][68];   // [d][q]
    __shared__ __align__(16) float Ks[64][68];   // [d][k]
    const int tid = threadIdx.x;
    const int bh = blockIdx.z, b = bh >> 4, h = bh & 15;
    const int q0 = blockIdx.y * 64, k0 = blockIdx.x * 64;
    const float sc = __expf(fminf(logit_scale[h], LOGMAX));

    #pragma unroll
    for (int l = 0; l < 4; ++l) {
        int idx = tid + l * 256;        // 0..1023 float4 slots
        int r = idx >> 4, c4 = idx & 15;
        float4 qv = *reinterpret_cast<const float4*>(
            &g_qkv[(size_t)(b * Nn + q0 + r) * THREEC + h * Dd + c4 * 4]);
        float4 kv = *reinterpret_cast<const float4*>(
            &g_qkv[(size_t)(b * Nn + k0 + r) * THREEC + Cc + h * Dd + c4 * 4]);
        Qs[c4 * 4 + 0][r] = qv.x; Qs[c4 * 4 + 1][r] = qv.y;
        Qs[c4 * 4 + 2][r] = qv.z; Qs[c4 * 4 + 3][r] = qv.w;
        Ks[c4 * 4 + 0][r] = kv.x; Ks[c4 * 4 + 1][r] = kv.y;
        Ks[c4 * 4 + 2][r] = kv.z; Ks[c4 * 4 + 3][r] = kv.w;
    }
    __syncthreads();

    const int tx = tid & 15, ty = tid >> 4;
    float acc[4][4] = {};
    #pragma unroll 16
    for (int k = 0; k < 64; ++k) {
        float4 a4 = *reinterpret_cast<const float4*>(&Qs[k][ty * 4]);
        float4 b4 = *reinterpret_cast<const float4*>(&Ks[k][tx * 4]);
        float a[4] = {a4.x, a4.y, a4.z, a4.w};
        float bb[4] = {b4.x, b4.y, b4.z, b4.w};
        #pragma unroll
        for (int i = 0; i < 4; ++i)
            #pragma unroll
            for (int j = 0; j < 4; ++j)
                acc[i][j] = fmaf(a[i], bb[j], acc[i][j]);
    }

    const size_t sbase = ((size_t)bh * Nn + q0) * Nn + k0;
    #pragma unroll
    for (int i = 0; i < 4; ++i) {
        int q = ty * 4 + i;
        #pragma unroll
        for (int j = 0; j < 4; ++j) {
            int kk = tx * 4 + j;
            float v = acc[i][j] * sc + alibi[sbase + (size_t)q * Nn + kk];
            if (mask[b * Nn + k0 + kk] != 0) v = neg_inf();
            g_scores[sbase + (size_t)q * Nn + kk] = v;
        }
    }
}

// ---------------------------------------------------------------------------
// Row softmax over the key axis (row length N=2048). One block per row.
// ---------------------------------------------------------------------------
__global__ __launch_bounds__(256) void softmax_kernel()
{
    __shared__ float red[8];
    const int tid = threadIdx.x;
    const int lane = tid & 31, wid = tid >> 5;
    float* p = g_scores + (size_t)blockIdx.x * Nn;

    float4 a = *reinterpret_cast<const float4*>(&p[tid * 4]);
    float4 c = *reinterpret_cast<const float4*>(&p[1024 + tid * 4]);
    float v[8] = {a.x, a.y, a.z, a.w, c.x, c.y, c.z, c.w};

    float mx = v[0];
    #pragma unroll
    for (int i = 1; i < 8; ++i) mx = fmaxf(mx, v[i]);
    #pragma unroll
    for (int o = 16; o; o >>= 1) mx = fmaxf(mx, __shfl_xor_sync(0xffffffffu, mx, o));
    if (lane == 0) red[wid] = mx;
    __syncthreads();
    if (wid == 0) {
        float m = (lane < 8) ? red[lane] : neg_inf();
        #pragma unroll
        for (int o = 4; o; o >>= 1) m = fmaxf(m, __shfl_xor_sync(0xffffffffu, m, o));
        if (lane == 0) red[0] = m;
    }
    __syncthreads();
    mx = red[0];

    float s = 0.f;
    #pragma unroll
    for (int i = 0; i < 8; ++i) { v[i] = __expf(v[i] - mx); s += v[i]; }
    #pragma unroll
    for (int o = 16; o; o >>= 1) s += __shfl_xor_sync(0xffffffffu, s, o);
    __syncthreads();
    if (lane == 0) red[wid] = s;
    __syncthreads();
    if (wid == 0) {
        float t = (lane < 8) ? red[lane] : 0.f;
        #pragma unroll
        for (int o = 4; o; o >>= 1) t += __shfl_xor_sync(0xffffffffu, t, o);
        if (lane == 0) red[0] = t;
    }
    __syncthreads();
    float inv = 1.0f / red[0];

    float4 o0 = {v[0] * inv, v[1] * inv, v[2] * inv, v[3] * inv};
    float4 o1 = {v[4] * inv, v[5] * inv, v[6] * inv, v[7] * inv};
    *reinterpret_cast<float4*>(&p[tid * 4]) = o0;
    *reinterpret_cast<float4*>(&p[1024 + tid * 4]) = o1;
}

// ---------------------------------------------------------------------------
// O = P @ V per (b,h): [2048 x 2048] @ [2048 x 64]. Writes [B,N,H*D] layout.
// ---------------------------------------------------------------------------
__global__ __launch_bounds__(256) void pv_kernel()
{
    __shared__ __align__(16) float Ss[16][68];   // [k][q]
    __shared__ __align__(16) float Vs[16][68];   // [k][d]
    const int tid = threadIdx.x;
    const int bh = blockIdx.z, b = bh >> 4, h = bh & 15;
    const int q0 = blockIdx.y * 64;
    const int tx = tid & 15, ty = tid >> 4;
    const int sr = tid >> 2, sc4 = tid & 3;      // S-tile loader
    const int vr = tid >> 4, vc4 = tid & 15;     // V-tile loader

    float acc[4][4] = {};

    for (int kt = 0; kt < Nn; kt += 16) {
        float4 sv = *reinterpret_cast<const float4*>(
            &g_scores[((size_t)bh * Nn + q0 + sr) * Nn + kt + sc4 * 4]);
        float4 vv = *reinterpret_cast<const float4*>(
            &g_qkv[(size_t)(b * Nn + kt + vr) * THREEC + 2 * Cc + h * Dd + vc4 * 4]);
        __syncthreads();
        Ss[sc4 * 4 + 0][sr] = sv.x; Ss[sc4 * 4 + 1][sr] = sv.y;
        Ss[sc4 * 4 + 2][sr] = sv.z; Ss[sc4 * 4 + 3][sr] = sv.w;
        *reinterpret_cast<float4*>(&Vs[vr][vc4 * 4]) = vv;
        __syncthreads();
        #pragma unroll
        for (int k = 0; k < 16; ++k) {
            float4 a4 = *reinterpret_cast<const float4*>(&Ss[k][ty * 4]);
            float4 b4 = *reinterpret_cast<const float4*>(&Vs[k][tx * 4]);
            float a[4] = {a4.x, a4.y, a4.z, a4.w};
            float bb[4] = {b4.x, b4.y, b4.z, b4.w};
            #pragma unroll
            for (int i = 0; i < 4; ++i)
                #pragma unroll
                for (int j = 0; j < 4; ++j)
                    acc[i][j] = fmaf(a[i], bb[j], acc[i][j]);
        }
    }

    #pragma unroll
    for (int i = 0; i < 4; ++i)
        #pragma unroll
        for (int j = 0; j < 4; ++j)
            g_att[(size_t)(b * Nn + q0 + ty * 4 + i) * Cc + h * Dd + tx * 4 + j] = acc[i][j];
}

// ---------------------------------------------------------------------------
// Launch
// ---------------------------------------------------------------------------
extern "C" void kernel_launch(void* const* d_in, const int* in_sizes, int n_in,
                              void* d_out, int out_size)
{
    const float* x           = (const float*)d_in[0];
    const int*   pad_mask    = (const int*)d_in[1];     // bool -> int32
    const float* alibi       = (const float*)d_in[2];
    const float* qkv_w       = (const float*)d_in[3];
    const float* proj_w      = (const float*)d_in[4];
    const float* proj_b      = (const float*)d_in[5];
    const float* logit_scale = (const float*)d_in[6];
    float*       out         = (float*)d_out;

    void *qkvp = nullptr, *attp = nullptr;
    cudaGetSymbolAddress(&qkvp, g_qkv);
    cudaGetSymbolAddress(&attp, g_att);

    // 1. qkv projection: [4096,1024] x [3072,1024]^T -> g_qkv
    sgemm_nt<<<dim3(THREEC / 64, MROWS / 64), 256>>>(
        x, qkv_w, nullptr, (float*)qkvp, MROWS, THREEC, Cc);

    // 2. normalize q and k head-rows in place
    norm_qk<<<(MROWS * 2 * Hh) / 8, 256>>>((float*)qkvp);

    // 3. scores + scale + alibi + mask
    scores_kernel<<<dim3(Nn / 64, Nn / 64, Bb * Hh), 256>>>(alibi, pad_mask, logit_scale);

    // 4. softmax along key axis
    softmax_kernel<<<Bb * Hh * Nn, 256>>>();

    // 5. O = P @ V
    pv_kernel<<<dim3(1, Nn / 64, Bb * Hh), 256>>>();

    // 6. output projection + bias
    sgemm_nt<<<dim3(Cc / 64, MROWS / 64), 256>>>(
        (const float*)attp, proj_w, proj_b, out, MROWS, Cc, Cc);
}

// round 10
// speedup vs baseline: 2.1026x; 2.1026x over previous
#include <cuda_runtime.h>
#include <math.h>
#include <stdint.h>

// Problem constants
#define Bb      2
#define Nn      2048
#define Cc      1024
#define Hh      16
#define Dd      64
#define MROWS   (Bb * Nn)      // 4096
#define THREEC  (3 * Cc)       // 3072
#define LOGMAX  4.6051701859880914f  // ln(100)

// ---------------------------------------------------------------------------
// Scratch
// ---------------------------------------------------------------------------
__device__ float g_qkv[(size_t)MROWS * THREEC];          // 50 MB
__device__ float g_scores[(size_t)Bb * Hh * Nn * Nn];    // 512 MB
__device__ float g_att[(size_t)MROWS * Cc];              // 16 MB

__device__ __forceinline__ float neg_inf() { return __int_as_float(0xff800000); }

// ---------------------------------------------------------------------------
// tf32 mma.sync helpers (sm_80+ PTX — no 'a'-suffix arch features needed)
// ---------------------------------------------------------------------------
__device__ __forceinline__ uint32_t f2t(float x) {
    uint32_t u;
    asm("cvt.rna.tf32.f32 %0, %1;" : "=r"(u) : "f"(x));
    return u;
}

// D(16x8) += A(16x8) * B(8x8);  A row-major frag, B col-major frag, f32 accum
__device__ __forceinline__ void mma8(float* d, const uint32_t* a, const uint32_t* b) {
    asm volatile(
        "mma.sync.aligned.m16n8k8.row.col.f32.tf32.tf32.f32 "
        "{%0,%1,%2,%3}, {%4,%5,%6,%7}, {%8,%9}, {%0,%1,%2,%3};"
        : "+f"(d[0]), "+f"(d[1]), "+f"(d[2]), "+f"(d[3])
        : "r"(a[0]), "r"(a[1]), "r"(a[2]), "r"(a[3]), "r"(b[0]), "r"(b[1]));
}
// Fragment maps (m16n8k8, lane g = lane>>2, tg = lane&3):
//   A: a0=(g,tg) a1=(g+8,tg) a2=(g,tg+4) a3=(g+8,tg+4)     [row, k]
//   B: b0=(k=tg,n=g) b1=(k=tg+4,n=g)                        [k, col]
//   C: c0=(g,2tg) c1=(g,2tg+1) c2=(g+8,2tg) c3=(g+8,2tg+1)  [row, col]

// ===========================================================================
// NT GEMM on tensor pipe: C[M][Nc] = A[M][K] * W[Nc][K]^T (+ bias)
// 256 thr, BM=128, BN=64, BK=16. Warp grid 4(m) x 2(n), warp tile 32x32.
// ===========================================================================
#define PITCH 20   // 20 mod 32 == 20 -> frag lds conflict-free (4g-spaced)

__global__ __launch_bounds__(256) void gemm_mma_nt(
    const float* __restrict__ A, const float* __restrict__ W,
    const float* __restrict__ bias, float* __restrict__ C,
    int M, int Nc, int K)
{
    __shared__ uint32_t As[128][PITCH];
    __shared__ uint32_t Bs[64][PITCH];
    const int tid = threadIdx.x;
    const int wid = tid >> 5, lane = tid & 31;
    const int g = lane >> 2, tg = lane & 3;
    const int wm = wid & 3, wn = wid >> 2;
    const int m0 = blockIdx.y * 128, n0 = blockIdx.x * 64;
    const int lr = tid >> 2, lc = tid & 3;      // loader row/col4

    float acc[2][4][4] = {};

    for (int kt = 0; kt < K; kt += 16) {
        float4 av0 = *reinterpret_cast<const float4*>(&A[(size_t)(m0 + lr) * K + kt + lc * 4]);
        float4 av1 = *reinterpret_cast<const float4*>(&A[(size_t)(m0 + lr + 64) * K + kt + lc * 4]);
        float4 wv  = *reinterpret_cast<const float4*>(&W[(size_t)(n0 + lr) * K + kt + lc * 4]);
        __syncthreads();
        As[lr][lc * 4 + 0] = f2t(av0.x); As[lr][lc * 4 + 1] = f2t(av0.y);
        As[lr][lc * 4 + 2] = f2t(av0.z); As[lr][lc * 4 + 3] = f2t(av0.w);
        As[lr + 64][lc * 4 + 0] = f2t(av1.x); As[lr + 64][lc * 4 + 1] = f2t(av1.y);
        As[lr + 64][lc * 4 + 2] = f2t(av1.z); As[lr + 64][lc * 4 + 3] = f2t(av1.w);
        Bs[lr][lc * 4 + 0] = f2t(wv.x); Bs[lr][lc * 4 + 1] = f2t(wv.y);
        Bs[lr][lc * 4 + 2] = f2t(wv.z); Bs[lr][lc * 4 + 3] = f2t(wv.w);
        __syncthreads();

        #pragma unroll
        for (int ks = 0; ks < 2; ++ks) {
            const int k0 = ks * 8;
            uint32_t af[2][4], bf[4][2];
            #pragma unroll
            for (int mt = 0; mt < 2; ++mt) {
                const int rb = wm * 32 + mt * 16;
                af[mt][0] = As[rb + g][k0 + tg];
                af[mt][1] = As[rb + g + 8][k0 + tg];
                af[mt][2] = As[rb + g][k0 + tg + 4];
                af[mt][3] = As[rb + g + 8][k0 + tg + 4];
            }
            #pragma unroll
            for (int nt = 0; nt < 4; ++nt) {
                const int nb = wn * 32 + nt * 8;
                bf[nt][0] = Bs[nb + g][k0 + tg];
                bf[nt][1] = Bs[nb + g][k0 + tg + 4];
            }
            #pragma unroll
            for (int mt = 0; mt < 2; ++mt)
                #pragma unroll
                for (int nt = 0; nt < 4; ++nt)
                    mma8(acc[mt][nt], af[mt], bf[nt]);
        }
    }

    #pragma unroll
    for (int mt = 0; mt < 2; ++mt) {
        const int row = m0 + wm * 32 + mt * 16 + g;
        #pragma unroll
        for (int nt = 0; nt < 4; ++nt) {
            const int col = n0 + wn * 32 + nt * 8 + tg * 2;
            float2 v0 = {acc[mt][nt][0], acc[mt][nt][1]};
            float2 v1 = {acc[mt][nt][2], acc[mt][nt][3]};
            if (bias) {
                float b0 = bias[col], b1 = bias[col + 1];
                v0.x += b0; v0.y += b1; v1.x += b0; v1.y += b1;
            }
            *reinterpret_cast<float2*>(&C[(size_t)row * Nc + col]) = v0;
            *reinterpret_cast<float2*>(&C[(size_t)(row + 8) * Nc + col]) = v1;
        }
    }
}

// ---------------------------------------------------------------------------
// Normalize q and k head-rows (D=64) in place. One warp per (row, s, h).
// ---------------------------------------------------------------------------
__global__ __launch_bounds__(256) void norm_qk(float* __restrict__ qkv)
{
    int warp = (blockIdx.x * blockDim.x + threadIdx.x) >> 5;
    int lane = threadIdx.x & 31;
    int m = warp >> 5;
    int rem = warp & 31;
    int s = rem >> 4;
    int h = rem & 15;
    float* row = qkv + (size_t)m * THREEC + s * Cc + h * Dd;
    float v0 = row[lane], v1 = row[lane + 32];
    float ss = v0 * v0 + v1 * v1;
    #pragma unroll
    for (int o = 16; o; o >>= 1) ss += __shfl_xor_sync(0xffffffffu, ss, o);
    float inv = rsqrtf(ss);
    row[lane] = v0 * inv;
    row[lane + 32] = v1 * inv;
}

// ===========================================================================
// Scores on tensor pipe: S = scale*(Qn Kn^T) + alibi, mask -> -inf
// 256 thr, 64(q) x 64(k) tile, k-dim = D = 64. Warp grid 2(m) x 4(n).
// ===========================================================================
__global__ __launch_bounds__(256) void scores_mma(
    const float* __restrict__ alibi,
    const int* __restrict__ mask,
    const float* __restrict__ logit_scale)
{
    __shared__ uint32_t Qs[64][68];   // 68 mod 32 == 4 -> conflict-free frags
    __shared__ uint32_t Ks[64][68];
    __shared__ int Ms[64];
    const int tid = threadIdx.x;
    const int wid = tid >> 5, lane = tid & 31;
    const int g = lane >> 2, tg = lane & 3;
    const int wm = wid & 1, wn = wid >> 1;
    const int bh = blockIdx.z, b = bh >> 4, h = bh & 15;
    const int q0 = blockIdx.y * 64, k0 = blockIdx.x * 64;
    const float sc = __expf(fminf(logit_scale[h], LOGMAX));

    #pragma unroll
    for (int l = 0; l < 4; ++l) {
        int slot = tid + l * 256;
        int r = slot >> 4, c4 = slot & 15;
        float4 qv = *reinterpret_cast<const float4*>(
            &g_qkv[(size_t)(b * Nn + q0 + r) * THREEC + h * Dd + c4 * 4]);
        float4 kv = *reinterpret_cast<const float4*>(
            &g_qkv[(size_t)(b * Nn + k0 + r) * THREEC + Cc + h * Dd + c4 * 4]);
        Qs[r][c4 * 4 + 0] = f2t(qv.x); Qs[r][c4 * 4 + 1] = f2t(qv.y);
        Qs[r][c4 * 4 + 2] = f2t(qv.z); Qs[r][c4 * 4 + 3] = f2t(qv.w);
        Ks[r][c4 * 4 + 0] = f2t(kv.x); Ks[r][c4 * 4 + 1] = f2t(kv.y);
        Ks[r][c4 * 4 + 2] = f2t(kv.z); Ks[r][c4 * 4 + 3] = f2t(kv.w);
    }
    if (tid < 64) Ms[tid] = mask[b * Nn + k0 + tid];
    __syncthreads();

    float acc[2][2][4] = {};
    #pragma unroll
    for (int ks = 0; ks < 8; ++ks) {
        const int kk0 = ks * 8;
        uint32_t af[2][4], bf[2][2];
        #pragma unroll
        for (int mt = 0; mt < 2; ++mt) {
            const int rb = wm * 32 + mt * 16;
            af[mt][0] = Qs[rb + g][kk0 + tg];
            af[mt][1] = Qs[rb + g + 8][kk0 + tg];
            af[mt][2] = Qs[rb + g][kk0 + tg + 4];
            af[mt][3] = Qs[rb + g + 8][kk0 + tg + 4];
        }
        #pragma unroll
        for (int nt = 0; nt < 2; ++nt) {
            const int nb = wn * 16 + nt * 8;
            bf[nt][0] = Ks[nb + g][kk0 + tg];
            bf[nt][1] = Ks[nb + g][kk0 + tg + 4];
        }
        #pragma unroll
        for (int mt = 0; mt < 2; ++mt)
            #pragma unroll
            for (int nt = 0; nt < 2; ++nt)
                mma8(acc[mt][nt], af[mt], bf[nt]);
    }

    const size_t sbase = ((size_t)bh * Nn + q0) * Nn + k0;
    #pragma unroll
    for (int mt = 0; mt < 2; ++mt) {
        const int q = wm * 32 + mt * 16 + g;
        #pragma unroll
        for (int nt = 0; nt < 2; ++nt) {
            const int kk = wn * 16 + nt * 8 + tg * 2;
            const bool msk0 = Ms[kk] != 0, msk1 = Ms[kk + 1] != 0;
            float2 al0 = *reinterpret_cast<const float2*>(&alibi[sbase + (size_t)q * Nn + kk]);
            float2 al1 = *reinterpret_cast<const float2*>(&alibi[sbase + (size_t)(q + 8) * Nn + kk]);
            float2 o0, o1;
            o0.x = msk0 ? neg_inf() : fmaf(acc[mt][nt][0], sc, al0.x);
            o0.y = msk1 ? neg_inf() : fmaf(acc[mt][nt][1], sc, al0.y);
            o1.x = msk0 ? neg_inf() : fmaf(acc[mt][nt][2], sc, al1.x);
            o1.y = msk1 ? neg_inf() : fmaf(acc[mt][nt][3], sc, al1.y);
            *reinterpret_cast<float2*>(&g_scores[sbase + (size_t)q * Nn + kk]) = o0;
            *reinterpret_cast<float2*>(&g_scores[sbase + (size_t)(q + 8) * Nn + kk]) = o1;
        }
    }
}

// ---------------------------------------------------------------------------
// Row softmax over key axis (N=2048). One block per row. (HBM-bound, 85% SOL)
// ---------------------------------------------------------------------------
__global__ __launch_bounds__(256) void softmax_kernel()
{
    __shared__ float red[8];
    const int tid = threadIdx.x;
    const int lane = tid & 31, wid = tid >> 5;
    float* p = g_scores + (size_t)blockIdx.x * Nn;

    float4 a = *reinterpret_cast<const float4*>(&p[tid * 4]);
    float4 c = *reinterpret_cast<const float4*>(&p[1024 + tid * 4]);
    float v[8] = {a.x, a.y, a.z, a.w, c.x, c.y, c.z, c.w};

    float mx = v[0];
    #pragma unroll
    for (int i = 1; i < 8; ++i) mx = fmaxf(mx, v[i]);
    #pragma unroll
    for (int o = 16; o; o >>= 1) mx = fmaxf(mx, __shfl_xor_sync(0xffffffffu, mx, o));
    if (lane == 0) red[wid] = mx;
    __syncthreads();
    if (wid == 0) {
        float m = (lane < 8) ? red[lane] : neg_inf();
        #pragma unroll
        for (int o = 4; o; o >>= 1) m = fmaxf(m, __shfl_xor_sync(0xffffffffu, m, o));
        if (lane == 0) red[0] = m;
    }
    __syncthreads();
    mx = red[0];

    float s = 0.f;
    #pragma unroll
    for (int i = 0; i < 8; ++i) { v[i] = __expf(v[i] - mx); s += v[i]; }
    #pragma unroll
    for (int o = 16; o; o >>= 1) s += __shfl_xor_sync(0xffffffffu, s, o);
    __syncthreads();
    if (lane == 0) red[wid] = s;
    __syncthreads();
    if (wid == 0) {
        float t = (lane < 8) ? red[lane] : 0.f;
        #pragma unroll
        for (int o = 4; o; o >>= 1) t += __shfl_xor_sync(0xffffffffu, t, o);
        if (lane == 0) red[0] = t;
    }
    __syncthreads();
    float inv = 1.0f / red[0];

    float4 o0 = {v[0] * inv, v[1] * inv, v[2] * inv, v[3] * inv};
    float4 o1 = {v[4] * inv, v[5] * inv, v[6] * inv, v[7] * inv};
    *reinterpret_cast<float4*>(&p[tid * 4]) = o0;
    *reinterpret_cast<float4*>(&p[1024 + tid * 4]) = o1;
}

// ===========================================================================
// PV on tensor pipe: O[q][d] = sum_k P[q][k] V[k][d]  (NN GEMM)
// 256 thr, BM=64(q), BN=64(d), BK=16, loop over N=2048.
// B-frag needs V col-major -> Vs[k][d] pitch 72 (8g+tg conflict-free).
// ===========================================================================
__global__ __launch_bounds__(256) void pv_mma()
{
    __shared__ uint32_t Ps[64][PITCH];
    __shared__ uint32_t Vs[16][72];
    const int tid = threadIdx.x;
    const int wid = tid >> 5, lane = tid & 31;
    const int g = lane >> 2, tg = lane & 3;
    const int wm = wid & 1, wn = wid >> 1;
    const int bh = blockIdx.z, b = bh >> 4, h = bh & 15;
    const int q0 = blockIdx.y * 64;
    const int pr = tid >> 2, pc = tid & 3;      // P loader
    const int vr = tid >> 4, vc = tid & 15;     // V loader

    float acc[2][2][4] = {};

    for (int kt = 0; kt < Nn; kt += 16) {
        float4 pv4 = *reinterpret_cast<const float4*>(
            &g_scores[((size_t)bh * Nn + q0 + pr) * Nn + kt + pc * 4]);
        float4 vv4 = *reinterpret_cast<const float4*>(
            &g_qkv[(size_t)(b * Nn + kt + vr) * THREEC + 2 * Cc + h * Dd + vc * 4]);
        __syncthreads();
        Ps[pr][pc * 4 + 0] = f2t(pv4.x); Ps[pr][pc * 4 + 1] = f2t(pv4.y);
        Ps[pr][pc * 4 + 2] = f2t(pv4.z); Ps[pr][pc * 4 + 3] = f2t(pv4.w);
        Vs[vr][vc * 4 + 0] = f2t(vv4.x); Vs[vr][vc * 4 + 1] = f2t(vv4.y);
        Vs[vr][vc * 4 + 2] = f2t(vv4.z); Vs[vr][vc * 4 + 3] = f2t(vv4.w);
        __syncthreads();

        #pragma unroll
        for (int ks = 0; ks < 2; ++ks) {
            const int k0 = ks * 8;
            uint32_t af[2][4], bf[2][2];
            #pragma unroll
            for (int mt = 0; mt < 2; ++mt) {
                const int rb = wm * 32 + mt * 16;
                af[mt][0] = Ps[rb + g][k0 + tg];
                af[mt][1] = Ps[rb + g + 8][k0 + tg];
                af[mt][2] = Ps[rb + g][k0 + tg + 4];
                af[mt][3] = Ps[rb + g + 8][k0 + tg + 4];
            }
            #pragma unroll
            for (int nt = 0; nt < 2; ++nt) {
                const int nb = wn * 16 + nt * 8;
                bf[nt][0] = Vs[k0 + tg][nb + g];
                bf[nt][1] = Vs[k0 + tg + 4][nb + g];
            }
            #pragma unroll
            for (int mt = 0; mt < 2; ++mt)
                #pragma unroll
                for (int nt = 0; nt < 2; ++nt)
                    mma8(acc[mt][nt], af[mt], bf[nt]);
        }
    }

    #pragma unroll
    for (int mt = 0; mt < 2; ++mt) {
        const int q = q0 + wm * 32 + mt * 16 + g;
        #pragma unroll
        for (int nt = 0; nt < 2; ++nt) {
            const int dcol = wn * 16 + nt * 8 + tg * 2;
            float2 v0 = {acc[mt][nt][0], acc[mt][nt][1]};
            float2 v1 = {acc[mt][nt][2], acc[mt][nt][3]};
            *reinterpret_cast<float2*>(&g_att[(size_t)(b * Nn + q) * Cc + h * Dd + dcol]) = v0;
            *reinterpret_cast<float2*>(&g_att[(size_t)(b * Nn + q + 8) * Cc + h * Dd + dcol]) = v1;
        }
    }
}

// ---------------------------------------------------------------------------
// Launch
// ---------------------------------------------------------------------------
extern "C" void kernel_launch(void* const* d_in, const int* in_sizes, int n_in,
                              void* d_out, int out_size)
{
    const float* x           = (const float*)d_in[0];
    const int*   pad_mask    = (const int*)d_in[1];
    const float* alibi       = (const float*)d_in[2];
    const float* qkv_w       = (const float*)d_in[3];
    const float* proj_w      = (const float*)d_in[4];
    const float* proj_b      = (const float*)d_in[5];
    const float* logit_scale = (const float*)d_in[6];
    float*       out         = (float*)d_out;

    void *qkvp = nullptr, *attp = nullptr;
    cudaGetSymbolAddress(&qkvp, g_qkv);
    cudaGetSymbolAddress(&attp, g_att);

    // 1. qkv projection (tf32 mma): [4096,1024] x [3072,1024]^T
    gemm_mma_nt<<<dim3(THREEC / 64, MROWS / 128), 256>>>(
        x, qkv_w, nullptr, (float*)qkvp, MROWS, THREEC, Cc);

    // 2. normalize q and k head-rows in place
    norm_qk<<<(MROWS * 2 * Hh) / 8, 256>>>((float*)qkvp);

    // 3. scores + scale + alibi + mask (tf32 mma)
    scores_mma<<<dim3(Nn / 64, Nn / 64, Bb * Hh), 256>>>(alibi, pad_mask, logit_scale);

    // 4. softmax along key axis
    softmax_kernel<<<Bb * Hh * Nn, 256>>>();

    // 5. O = P @ V (tf32 mma)
    pv_mma<<<dim3(1, Nn / 64, Bb * Hh), 256>>>();

    // 6. output projection + bias (tf32 mma)
    gemm_mma_nt<<<dim3(Cc / 64, MROWS / 128), 256>>>(
        (const float*)attp, proj_w, proj_b, out, MROWS, Cc, Cc);
}

// round 11
// speedup vs baseline: 2.9862x; 1.4202x over previous
#include <cuda_runtime.h>
#include <math.h>
#include <stdint.h>

// Problem constants
#define Bb      2
#define Nn      2048
#define Cc      1024
#define Hh      16
#define Dd      64
#define MROWS   (Bb * Nn)      // 4096
#define THREEC  (3 * Cc)       // 3072
#define LOGMAX  4.6051701859880914f  // ln(100)
#define MASKNEG (-1e30f)

// ---------------------------------------------------------------------------
// Scratch
// ---------------------------------------------------------------------------
__device__ float g_qkv[(size_t)MROWS * THREEC];          // 50 MB
__device__ float g_att[(size_t)MROWS * Cc];              // 16 MB

// ---------------------------------------------------------------------------
// tf32 mma.sync helpers (sm_80+ PTX — safe under compute_103 family target)
// ---------------------------------------------------------------------------
__device__ __forceinline__ uint32_t f2t(float x) {
    uint32_t u;
    asm("cvt.rna.tf32.f32 %0, %1;" : "=r"(u) : "f"(x));
    return u;
}

// D(16x8) += A(16x8) * B(8x8); A row frag, B col frag, f32 accum
__device__ __forceinline__ void mma8(float* d, const uint32_t* a, const uint32_t* b) {
    asm volatile(
        "mma.sync.aligned.m16n8k8.row.col.f32.tf32.tf32.f32 "
        "{%0,%1,%2,%3}, {%4,%5,%6,%7}, {%8,%9}, {%0,%1,%2,%3};"
        : "+f"(d[0]), "+f"(d[1]), "+f"(d[2]), "+f"(d[3])
        : "r"(a[0]), "r"(a[1]), "r"(a[2]), "r"(a[3]), "r"(b[0]), "r"(b[1]));
}
// Frag maps (g = lane>>2, tg = lane&3):
//   A: a0=(g,tg) a1=(g+8,tg) a2=(g,tg+4) a3=(g+8,tg+4)      [row, k]
//   B: b0=(k=tg,n=g) b1=(k=tg+4,n=g)                         [k, col]
//   C: c0=(g,2tg) c1=(g,2tg+1) c2=(g+8,2tg) c3=(g+8,2tg+1)   [row, col]

// ===========================================================================
// NT GEMM on tensor pipe: C[M][Nc] = A[M][K] * W[Nc][K]^T (+ bias)
// 256 thr, BM=128, BN=64, BK=16. Warp grid 4(m) x 2(n), warp tile 32x32.
// ===========================================================================
#define PITCH 20

__global__ __launch_bounds__(256) void gemm_mma_nt(
    const float* __restrict__ A, const float* __restrict__ W,
    const float* __restrict__ bias, float* __restrict__ C,
    int M, int Nc, int K)
{
    __shared__ uint32_t As[128][PITCH];
    __shared__ uint32_t Bs[64][PITCH];
    const int tid = threadIdx.x;
    const int wid = tid >> 5, lane = tid & 31;
    const int g = lane >> 2, tg = lane & 3;
    const int wm = wid & 3, wn = wid >> 2;
    const int m0 = blockIdx.y * 128, n0 = blockIdx.x * 64;
    const int lr = tid >> 2, lc = tid & 3;

    float acc[2][4][4] = {};

    for (int kt = 0; kt < K; kt += 16) {
        float4 av0 = *reinterpret_cast<const float4*>(&A[(size_t)(m0 + lr) * K + kt + lc * 4]);
        float4 av1 = *reinterpret_cast<const float4*>(&A[(size_t)(m0 + lr + 64) * K + kt + lc * 4]);
        float4 wv  = *reinterpret_cast<const float4*>(&W[(size_t)(n0 + lr) * K + kt + lc * 4]);
        __syncthreads();
        As[lr][lc * 4 + 0] = f2t(av0.x); As[lr][lc * 4 + 1] = f2t(av0.y);
        As[lr][lc * 4 + 2] = f2t(av0.z); As[lr][lc * 4 + 3] = f2t(av0.w);
        As[lr + 64][lc * 4 + 0] = f2t(av1.x); As[lr + 64][lc * 4 + 1] = f2t(av1.y);
        As[lr + 64][lc * 4 + 2] = f2t(av1.z); As[lr + 64][lc * 4 + 3] = f2t(av1.w);
        Bs[lr][lc * 4 + 0] = f2t(wv.x); Bs[lr][lc * 4 + 1] = f2t(wv.y);
        Bs[lr][lc * 4 + 2] = f2t(wv.z); Bs[lr][lc * 4 + 3] = f2t(wv.w);
        __syncthreads();

        #pragma unroll
        for (int ks = 0; ks < 2; ++ks) {
            const int k0 = ks * 8;
            uint32_t af[2][4], bf[4][2];
            #pragma unroll
            for (int mt = 0; mt < 2; ++mt) {
                const int rb = wm * 32 + mt * 16;
                af[mt][0] = As[rb + g][k0 + tg];
                af[mt][1] = As[rb + g + 8][k0 + tg];
                af[mt][2] = As[rb + g][k0 + tg + 4];
                af[mt][3] = As[rb + g + 8][k0 + tg + 4];
            }
            #pragma unroll
            for (int nt = 0; nt < 4; ++nt) {
                const int nb = wn * 32 + nt * 8;
                bf[nt][0] = Bs[nb + g][k0 + tg];
                bf[nt][1] = Bs[nb + g][k0 + tg + 4];
            }
            #pragma unroll
            for (int mt = 0; mt < 2; ++mt)
                #pragma unroll
                for (int nt = 0; nt < 4; ++nt)
                    mma8(acc[mt][nt], af[mt], bf[nt]);
        }
    }

    #pragma unroll
    for (int mt = 0; mt < 2; ++mt) {
        const int row = m0 + wm * 32 + mt * 16 + g;
        #pragma unroll
        for (int nt = 0; nt < 4; ++nt) {
            const int col = n0 + wn * 32 + nt * 8 + tg * 2;
            float2 v0 = {acc[mt][nt][0], acc[mt][nt][1]};
            float2 v1 = {acc[mt][nt][2], acc[mt][nt][3]};
            if (bias) {
                float b0 = bias[col], b1 = bias[col + 1];
                v0.x += b0; v0.y += b1; v1.x += b0; v1.y += b1;
            }
            *reinterpret_cast<float2*>(&C[(size_t)row * Nc + col]) = v0;
            *reinterpret_cast<float2*>(&C[(size_t)(row + 8) * Nc + col]) = v1;
        }
    }
}

// ---------------------------------------------------------------------------
// Normalize q and k head-rows (D=64) in place. One warp per (row, s, h).
// ---------------------------------------------------------------------------
__global__ __launch_bounds__(256) void norm_qk(float* __restrict__ qkv)
{
    int warp = (blockIdx.x * blockDim.x + threadIdx.x) >> 5;
    int lane = threadIdx.x & 31;
    int m = warp >> 5;
    int rem = warp & 31;
    int s = rem >> 4;
    int h = rem & 15;
    float* row = qkv + (size_t)m * THREEC + s * Cc + h * Dd;
    float v0 = row[lane], v1 = row[lane + 32];
    float ss = v0 * v0 + v1 * v1;
    #pragma unroll
    for (int o = 16; o; o >>= 1) ss += __shfl_xor_sync(0xffffffffu, ss, o);
    float inv = rsqrtf(ss);
    row[lane] = v0 * inv;
    row[lane + 32] = v1 * inv;
}

// ===========================================================================
// Fused flash attention: per (bh, q-tile 64) block, stream k-chunks of 64.
// S = scale*(Qn Kn^T) + alibi + maskadd  ->  online softmax  ->  O += P V
// 128 threads, 4 warps; warp w owns q-rows [w*16, w*16+16).
// Scores never touch DRAM. KP smem buffer holds K, then is reused for P.
// ===========================================================================
__global__ __launch_bounds__(128) void attn_fused(
    const float* __restrict__ alibi,
    const int* __restrict__ mask,
    const float* __restrict__ logit_scale)
{
    __shared__ uint32_t KP[64][68];   // K chunk (tf32), then P (tf32)
    __shared__ uint32_t Vs[64][72];   // V chunk (tf32), pitch 72: B-frag conflict-free
    __shared__ float    Ms[64];       // additive mask: 0 or -1e30

    const int tid = threadIdx.x;
    const int wid = tid >> 5, lane = tid & 31;
    const int g = lane >> 2, tg = lane & 3;
    const int wq = wid * 16;                 // warp's q-row base in tile
    const int bh = blockIdx.y, b = bh >> 4, h = bh & 15;
    const int q0 = blockIdx.x * 64;
    const float sc = __expf(fminf(logit_scale[h], LOGMAX));

    // ---- stage Q tile (64x64) into KP, pull A-frags into registers ----
    #pragma unroll
    for (int i = 0; i < 8; ++i) {
        int slot = tid + i * 128;
        int r = slot >> 4, c4 = slot & 15;
        float4 qv = *reinterpret_cast<const float4*>(
            &g_qkv[(size_t)(b * Nn + q0 + r) * THREEC + h * Dd + c4 * 4]);
        KP[r][c4 * 4 + 0] = f2t(qv.x); KP[r][c4 * 4 + 1] = f2t(qv.y);
        KP[r][c4 * 4 + 2] = f2t(qv.z); KP[r][c4 * 4 + 3] = f2t(qv.w);
    }
    __syncthreads();
    uint32_t qf[8][4];
    #pragma unroll
    for (int ks = 0; ks < 8; ++ks) {
        qf[ks][0] = KP[wq + g][ks * 8 + tg];
        qf[ks][1] = KP[wq + g + 8][ks * 8 + tg];
        qf[ks][2] = KP[wq + g][ks * 8 + tg + 4];
        qf[ks][3] = KP[wq + g + 8][ks * 8 + tg + 4];
    }

    // online softmax state: rows (wq+g) and (wq+g+8)
    float m0r = MASKNEG, m1r = MASKNEG, l0 = 0.f, l1 = 0.f;
    float acc_o[8][4] = {};

    const float* al0 = &alibi[((size_t)bh * Nn + q0 + wq + g) * Nn];
    const float* al1 = al0 + (size_t)8 * Nn;

    for (int kt = 0; kt < Nn; kt += 64) {
        __syncthreads();   // prior PV (KP=P, Vs) fully consumed
        // ---- load K & V chunk (64 rows x 64), mask ----
        #pragma unroll
        for (int i = 0; i < 8; ++i) {
            int slot = tid + i * 128;
            int r = slot >> 4, c4 = slot & 15;
            const float* base = &g_qkv[(size_t)(b * Nn + kt + r) * THREEC + h * Dd];
            float4 kv = *reinterpret_cast<const float4*>(base + Cc + c4 * 4);
            float4 vv = *reinterpret_cast<const float4*>(base + 2 * Cc + c4 * 4);
            KP[r][c4 * 4 + 0] = f2t(kv.x); KP[r][c4 * 4 + 1] = f2t(kv.y);
            KP[r][c4 * 4 + 2] = f2t(kv.z); KP[r][c4 * 4 + 3] = f2t(kv.w);
            Vs[r][c4 * 4 + 0] = f2t(vv.x); Vs[r][c4 * 4 + 1] = f2t(vv.y);
            Vs[r][c4 * 4 + 2] = f2t(vv.z); Vs[r][c4 * 4 + 3] = f2t(vv.w);
        }
        if (tid < 64) Ms[tid] = mask[b * Nn + kt + tid] ? MASKNEG : 0.f;
        __syncthreads();

        // ---- S = Q K^T (16 q x 64 k per warp) ----
        float s[8][4] = {};
        #pragma unroll
        for (int nt = 0; nt < 8; ++nt) {
            #pragma unroll
            for (int ks = 0; ks < 8; ++ks) {
                uint32_t bf[2];
                bf[0] = KP[nt * 8 + g][ks * 8 + tg];
                bf[1] = KP[nt * 8 + g][ks * 8 + tg + 4];
                mma8(s[nt], qf[ks], bf);
            }
        }

        // ---- scale + alibi + mask; chunk row max ----
        float cm0 = MASKNEG, cm1 = MASKNEG;
        #pragma unroll
        for (int j = 0; j < 8; ++j) {
            const int col = j * 8 + tg * 2;
            float2 a0 = *reinterpret_cast<const float2*>(&al0[kt + col]);
            float2 a1 = *reinterpret_cast<const float2*>(&al1[kt + col]);
            float msk0 = Ms[col], msk1 = Ms[col + 1];
            s[j][0] = fmaf(s[j][0], sc, a0.x + msk0);
            s[j][1] = fmaf(s[j][1], sc, a0.y + msk1);
            s[j][2] = fmaf(s[j][2], sc, a1.x + msk0);
            s[j][3] = fmaf(s[j][3], sc, a1.y + msk1);
            cm0 = fmaxf(cm0, fmaxf(s[j][0], s[j][1]));
            cm1 = fmaxf(cm1, fmaxf(s[j][2], s[j][3]));
        }
        cm0 = fmaxf(cm0, __shfl_xor_sync(0xffffffffu, cm0, 1));
        cm0 = fmaxf(cm0, __shfl_xor_sync(0xffffffffu, cm0, 2));
        cm1 = fmaxf(cm1, __shfl_xor_sync(0xffffffffu, cm1, 1));
        cm1 = fmaxf(cm1, __shfl_xor_sync(0xffffffffu, cm1, 2));

        const float nm0 = fmaxf(m0r, cm0), nm1 = fmaxf(m1r, cm1);
        const float f0 = __expf(m0r - nm0), f1 = __expf(m1r - nm1);
        m0r = nm0; m1r = nm1;

        float rs0 = 0.f, rs1 = 0.f;
        #pragma unroll
        for (int j = 0; j < 8; ++j) {
            s[j][0] = __expf(s[j][0] - nm0); rs0 += s[j][0];
            s[j][1] = __expf(s[j][1] - nm0); rs0 += s[j][1];
            s[j][2] = __expf(s[j][2] - nm1); rs1 += s[j][2];
            s[j][3] = __expf(s[j][3] - nm1); rs1 += s[j][3];
        }
        rs0 += __shfl_xor_sync(0xffffffffu, rs0, 1);
        rs0 += __shfl_xor_sync(0xffffffffu, rs0, 2);
        rs1 += __shfl_xor_sync(0xffffffffu, rs1, 1);
        rs1 += __shfl_xor_sync(0xffffffffu, rs1, 2);
        l0 = l0 * f0 + rs0;
        l1 = l1 * f1 + rs1;

        #pragma unroll
        for (int j = 0; j < 8; ++j) {
            acc_o[j][0] *= f0; acc_o[j][1] *= f0;
            acc_o[j][2] *= f1; acc_o[j][3] *= f1;
        }

        __syncthreads();   // all warps done reading K from KP
        // ---- write P into KP (own rows only) ----
        #pragma unroll
        for (int j = 0; j < 8; ++j) {
            KP[wq + g][j * 8 + tg * 2]     = f2t(s[j][0]);
            KP[wq + g][j * 8 + tg * 2 + 1] = f2t(s[j][1]);
            KP[wq + g + 8][j * 8 + tg * 2]     = f2t(s[j][2]);
            KP[wq + g + 8][j * 8 + tg * 2 + 1] = f2t(s[j][3]);
        }
        __syncwarp();

        // ---- O += P V ----
        #pragma unroll
        for (int ks = 0; ks < 8; ++ks) {
            uint32_t pf[4];
            pf[0] = KP[wq + g][ks * 8 + tg];
            pf[1] = KP[wq + g + 8][ks * 8 + tg];
            pf[2] = KP[wq + g][ks * 8 + tg + 4];
            pf[3] = KP[wq + g + 8][ks * 8 + tg + 4];
            #pragma unroll
            for (int nt = 0; nt < 8; ++nt) {
                uint32_t bf[2];
                bf[0] = Vs[ks * 8 + tg][nt * 8 + g];
                bf[1] = Vs[ks * 8 + tg + 4][nt * 8 + g];
                mma8(acc_o[nt], pf, bf);
            }
        }
    }

    // ---- normalize and write O in [B,N,H*D] layout ----
    const float il0 = 1.0f / l0, il1 = 1.0f / l1;
    const size_t row0 = (size_t)(b * Nn + q0 + wq + g) * Cc + h * Dd;
    const size_t row1 = row0 + (size_t)8 * Cc;
    #pragma unroll
    for (int j = 0; j < 8; ++j) {
        const int col = j * 8 + tg * 2;
        float2 v0 = {acc_o[j][0] * il0, acc_o[j][1] * il0};
        float2 v1 = {acc_o[j][2] * il1, acc_o[j][3] * il1};
        *reinterpret_cast<float2*>(&g_att[row0 + col]) = v0;
        *reinterpret_cast<float2*>(&g_att[row1 + col]) = v1;
    }
}

// ---------------------------------------------------------------------------
// Launch
// ---------------------------------------------------------------------------
extern "C" void kernel_launch(void* const* d_in, const int* in_sizes, int n_in,
                              void* d_out, int out_size)
{
    const float* x           = (const float*)d_in[0];
    const int*   pad_mask    = (const int*)d_in[1];
    const float* alibi       = (const float*)d_in[2];
    const float* qkv_w       = (const float*)d_in[3];
    const float* proj_w      = (const float*)d_in[4];
    const float* proj_b      = (const float*)d_in[5];
    const float* logit_scale = (const float*)d_in[6];
    float*       out         = (float*)d_out;

    void *qkvp = nullptr, *attp = nullptr;
    cudaGetSymbolAddress(&qkvp, g_qkv);
    cudaGetSymbolAddress(&attp, g_att);

    // 1. qkv projection (tf32 mma)
    gemm_mma_nt<<<dim3(THREEC / 64, MROWS / 128), 256>>>(
        x, qkv_w, nullptr, (float*)qkvp, MROWS, THREEC, Cc);

    // 2. normalize q and k head-rows in place
    norm_qk<<<(MROWS * 2 * Hh) / 8, 256>>>((float*)qkvp);

    // 3-5. fused scores + softmax + PV (no score materialization)
    attn_fused<<<dim3(Nn / 64, Bb * Hh), 128>>>(alibi, pad_mask, logit_scale);

    // 6. output projection + bias (tf32 mma)
    gemm_mma_nt<<<dim3(Cc / 64, MROWS / 128), 256>>>(
        (const float*)attp, proj_w, proj_b, out, MROWS, Cc, Cc);
}